// round 2
// baseline (speedup 1.0000x reference)
#include <cuda_runtime.h>
#include <cuda_bf16.h>

#define NN 100000
#define DD 64
#define EMAX 1000000

// ---------------- device scratch (no allocation allowed) ----------------
__device__ float g_h0[NN * DD];
__device__ float g_h1[NN * DD];
__device__ int   g_deg[NN];
__device__ int   g_rowptr[NN + 1];
__device__ int   g_cursor[NN];
__device__ int   g_col[EMAX];

// ---------------- CSR build ----------------
__global__ void k_zero(int* p, int n) {
    for (int i = blockIdx.x * blockDim.x + threadIdx.x; i < n; i += gridDim.x * blockDim.x)
        p[i] = 0;
}

__global__ void k_hist(const int* __restrict__ dst, int* __restrict__ deg, int E) {
    for (int e = blockIdx.x * blockDim.x + threadIdx.x; e < E; e += gridDim.x * blockDim.x)
        atomicAdd(&deg[dst[e]], 1);
}

// single-block exclusive scan of deg -> rowptr (and cursor copy)
__global__ void k_scan(const int* __restrict__ deg, int* __restrict__ rowptr,
                       int* __restrict__ cursor, int n) {
    __shared__ int ps[1024];
    int t = threadIdx.x;
    int chunk = (n + 1023) >> 10;
    int s0 = t * chunk;
    int s1 = min(s0 + chunk, n);
    int s = 0;
    for (int i = s0; i < s1; i++) s += deg[i];
    ps[t] = s;
    __syncthreads();
    // Hillis-Steele inclusive scan
    for (int d = 1; d < 1024; d <<= 1) {
        int v = (t >= d) ? ps[t - d] : 0;
        __syncthreads();
        ps[t] += v;
        __syncthreads();
    }
    int run = (t == 0) ? 0 : ps[t - 1];
    for (int i = s0; i < s1; i++) {
        rowptr[i] = run;
        cursor[i] = run;
        run += deg[i];
    }
    if (t == 0) rowptr[n] = ps[1023];
}

__global__ void k_scatter(const int* __restrict__ src, const int* __restrict__ dst,
                          int* __restrict__ cursor, int* __restrict__ col, int E) {
    for (int e = blockIdx.x * blockDim.x + threadIdx.x; e < E; e += gridDim.x * blockDim.x) {
        int d = dst[e];
        int p = atomicAdd(&cursor[d], 1);
        col[p] = src[e];
    }
}

// ---------------- node linear: out = x @ W^T + b ----------------
// 64 threads per node, thread j computes output column j. W row j in registers.
__global__ __launch_bounds__(256, 2) void k_lin(
    const float* __restrict__ x, const float* __restrict__ W,
    const float* __restrict__ b, float* __restrict__ out, int n) {
    __shared__ __align__(16) float hs[4][DD];
    int tid = threadIdx.x;
    int g = tid >> 6;
    int j = tid & 63;

    float w[DD];
#pragma unroll
    for (int k = 0; k < DD; k += 4) {
        float4 a = *(const float4*)&W[j * DD + k];
        w[k] = a.x; w[k + 1] = a.y; w[k + 2] = a.z; w[k + 3] = a.w;
    }
    float bj = b[j];

    for (int base = blockIdx.x * 4; base < n; base += gridDim.x * 4) {
        int i = base + g;
        if (i < n) hs[g][j] = x[i * DD + j];
        __syncthreads();
        if (i < n) {
            const float4* h4 = (const float4*)hs[g];
            float a0 = 0.f, a1 = 0.f, a2 = 0.f, a3 = 0.f;
#pragma unroll
            for (int k4 = 0; k4 < 16; k4++) {
                float4 hv = h4[k4];
                a0 += hv.x * w[k4 * 4 + 0];
                a1 += hv.y * w[k4 * 4 + 1];
                a2 += hv.z * w[k4 * 4 + 2];
                a3 += hv.w * w[k4 * 4 + 3];
            }
            out[i * DD + j] = (a0 + a1) + (a2 + a3) + bj;
        }
        __syncthreads();
    }
}

// ---------------- fused SAGE layer ----------------
// out[i] = act( mean_agg(h)[i] @ Wl^T + bl + h[i] @ Wr^T )
// 64 threads/node; thread j holds Wl row j and Wr row j in registers (128 regs).
__global__ __launch_bounds__(256, 1) void k_conv(
    const float* __restrict__ h, const int* __restrict__ rowptr,
    const int* __restrict__ col, const float* __restrict__ Wl,
    const float* __restrict__ bl, const float* __restrict__ Wr,
    float* __restrict__ out, int n, int do_relu) {
    __shared__ __align__(16) float aggs[4][DD];
    __shared__ __align__(16) float hs[4][DD];
    int tid = threadIdx.x;
    int g = tid >> 6;
    int j = tid & 63;

    float wl[DD], wr[DD];
#pragma unroll
    for (int k = 0; k < DD; k += 4) {
        float4 a = *(const float4*)&Wl[j * DD + k];
        wl[k] = a.x; wl[k + 1] = a.y; wl[k + 2] = a.z; wl[k + 3] = a.w;
        float4 c = *(const float4*)&Wr[j * DD + k];
        wr[k] = c.x; wr[k + 1] = c.y; wr[k + 2] = c.z; wr[k + 3] = c.w;
    }
    float bj = bl[j];

    for (int base = blockIdx.x * 4; base < n; base += gridDim.x * 4) {
        int i = base + g;
        if (i < n) {
            int s = rowptr[i];
            int e = rowptr[i + 1];
            int deg = e - s;
            float sum = 0.f;
            int nn = s;
            for (; nn + 4 <= e; nn += 4) {
                int c0 = col[nn], c1 = col[nn + 1], c2 = col[nn + 2], c3 = col[nn + 3];
                float v0 = h[c0 * DD + j];
                float v1 = h[c1 * DD + j];
                float v2 = h[c2 * DD + j];
                float v3 = h[c3 * DD + j];
                sum += (v0 + v1) + (v2 + v3);
            }
            for (; nn < e; nn++) sum += h[col[nn] * DD + j];
            aggs[g][j] = (deg > 0) ? (sum / (float)deg) : 0.f;
            hs[g][j] = h[i * DD + j];
        }
        __syncthreads();
        if (i < n) {
            const float4* a4 = (const float4*)aggs[g];
            const float4* h4 = (const float4*)hs[g];
            float a0 = 0.f, a1 = 0.f, a2 = 0.f, a3 = 0.f;
#pragma unroll
            for (int k4 = 0; k4 < 16; k4++) {
                float4 av = a4[k4];
                float4 hv = h4[k4];
                a0 += av.x * wl[k4 * 4 + 0];
                a1 += av.y * wl[k4 * 4 + 1];
                a2 += av.z * wl[k4 * 4 + 2];
                a3 += av.w * wl[k4 * 4 + 3];
                a0 += hv.x * wr[k4 * 4 + 0];
                a1 += hv.y * wr[k4 * 4 + 1];
                a2 += hv.z * wr[k4 * 4 + 2];
                a3 += hv.w * wr[k4 * 4 + 3];
            }
            float r = (a0 + a1) + (a2 + a3) + bj;
            if (do_relu) r = fmaxf(r, 0.f);
            out[i * DD + j] = r;
        }
        __syncthreads();
    }
}

// ---------------- edge dot product ----------------
__global__ void k_edge(const float* __restrict__ h, const int* __restrict__ ea,
                       const int* __restrict__ eb, float* __restrict__ out, int E) {
    int w = (blockIdx.x * blockDim.x + threadIdx.x) >> 5;
    int lane = threadIdx.x & 31;
    if (w >= E) return;
    int a = ea[w];
    int b = eb[w];
    float p = h[a * DD + lane] * h[b * DD + lane]
            + h[a * DD + 32 + lane] * h[b * DD + 32 + lane];
#pragma unroll
    for (int o = 16; o > 0; o >>= 1) p += __shfl_down_sync(0xffffffffu, p, o);
    if (lane == 0) out[w] = p;
}

// ---------------- launch ----------------
extern "C" void kernel_launch(void* const* d_in, const int* in_sizes, int n_in,
                              void* d_out, int out_size) {
    const float* x     = (const float*)d_in[0];
    const int*   ei    = (const int*)d_in[1];
    const int*   eli   = (const int*)d_in[2];
    const float* W_lin = (const float*)d_in[3];
    const float* b_lin = (const float*)d_in[4];
    const float* Wl1   = (const float*)d_in[5];
    const float* bl1   = (const float*)d_in[6];
    const float* Wr1   = (const float*)d_in[7];
    const float* Wl2   = (const float*)d_in[8];
    const float* bl2   = (const float*)d_in[9];
    const float* Wr2   = (const float*)d_in[10];

    int N  = in_sizes[0] / DD;      // 100000
    int E  = in_sizes[1] / 2;       // 1000000
    int EL = in_sizes[2] / 2;       // 200000

    const int* src = ei;            // edge_index[0] = source
    const int* dst = ei + E;        // edge_index[1] = target
    const int* ea  = eli;
    const int* eb  = eli + EL;

    float *h0, *h1;
    int *deg, *rowptr, *cursor, *col;
    cudaGetSymbolAddress((void**)&h0, g_h0);
    cudaGetSymbolAddress((void**)&h1, g_h1);
    cudaGetSymbolAddress((void**)&deg, g_deg);
    cudaGetSymbolAddress((void**)&rowptr, g_rowptr);
    cudaGetSymbolAddress((void**)&cursor, g_cursor);
    cudaGetSymbolAddress((void**)&col, g_col);

    float* preds = (float*)d_out;

    // CSR build
    k_zero<<<256, 256>>>(deg, N);
    k_hist<<<2048, 256>>>(dst, deg, E);
    k_scan<<<1, 1024>>>(deg, rowptr, cursor, N);
    k_scatter<<<2048, 256>>>(src, dst, cursor, col, E);

    // node_lin
    k_lin<<<592, 256>>>(x, W_lin, b_lin, h0, N);

    // conv1 (relu), conv2 (no relu; reuse h0 as output buffer)
    k_conv<<<592, 256>>>(h0, rowptr, col, Wl1, bl1, Wr1, h1, N, 1);
    k_conv<<<592, 256>>>(h1, rowptr, col, Wl2, bl2, Wr2, h0, N, 0);

    // edge classifier
    int blocks = (EL * 32 + 255) / 256;
    k_edge<<<blocks, 256>>>(h0, ea, eb, preds, EL);
}

// round 3
// speedup vs baseline: 2.3236x; 2.3236x over previous
#include <cuda_runtime.h>
#include <cuda_bf16.h>

#define NN 100000
#define DD 64
#define EMAX 1000000

// ---------------- device scratch (no allocation allowed) ----------------
__device__ float g_h0[NN * DD];
__device__ float g_h1[NN * DD];
__device__ float g_agg[NN * DD];
__device__ int   g_deg[NN];
__device__ int   g_rowptr[NN + 1];
__device__ int   g_cursor[NN];
__device__ int   g_col[EMAX];

// ---------------- CSR build ----------------
__global__ void k_zero(int* p, int n) {
    for (int i = blockIdx.x * blockDim.x + threadIdx.x; i < n; i += gridDim.x * blockDim.x)
        p[i] = 0;
}

__global__ void k_hist(const int* __restrict__ dst, int* __restrict__ deg, int E) {
    for (int e = blockIdx.x * blockDim.x + threadIdx.x; e < E; e += gridDim.x * blockDim.x)
        atomicAdd(&deg[dst[e]], 1);
}

// single-block exclusive scan of deg -> rowptr (and cursor copy)
__global__ void k_scan(const int* __restrict__ deg, int* __restrict__ rowptr,
                       int* __restrict__ cursor, int n) {
    __shared__ int ps[1024];
    int t = threadIdx.x;
    int chunk = (n + 1023) >> 10;
    int s0 = t * chunk;
    int s1 = min(s0 + chunk, n);
    int s = 0;
    for (int i = s0; i < s1; i++) s += deg[i];
    ps[t] = s;
    __syncthreads();
    for (int d = 1; d < 1024; d <<= 1) {
        int v = (t >= d) ? ps[t - d] : 0;
        __syncthreads();
        ps[t] += v;
        __syncthreads();
    }
    int run = (t == 0) ? 0 : ps[t - 1];
    for (int i = s0; i < s1; i++) {
        rowptr[i] = run;
        cursor[i] = run;
        run += deg[i];
    }
    if (t == 0) rowptr[n] = ps[1023];
}

__global__ void k_scatter(const int* __restrict__ src, const int* __restrict__ dst,
                          int* __restrict__ cursor, int* __restrict__ col, int E) {
    for (int e = blockIdx.x * blockDim.x + threadIdx.x; e < E; e += gridDim.x * blockDim.x) {
        int d = dst[e];
        int p = atomicAdd(&cursor[d], 1);
        col[p] = src[e];
    }
}

// ---------------- mean aggregation: warp per node ----------------
__global__ __launch_bounds__(256) void k_agg(
    const float* __restrict__ h, const int* __restrict__ rowptr,
    const int* __restrict__ col, float* __restrict__ agg, int n) {
    int w = (blockIdx.x * blockDim.x + threadIdx.x) >> 5;
    int lane = threadIdx.x & 31;
    if (w >= n) return;
    int s = rowptr[w];
    int e = rowptr[w + 1];
    float sx = 0.f, sy = 0.f;
    int nn = s;
    for (; nn + 4 <= e; nn += 4) {
        int c0 = col[nn], c1 = col[nn + 1], c2 = col[nn + 2], c3 = col[nn + 3];
        float2 v0 = ((const float2*)(h + c0 * DD))[lane];
        float2 v1 = ((const float2*)(h + c1 * DD))[lane];
        float2 v2 = ((const float2*)(h + c2 * DD))[lane];
        float2 v3 = ((const float2*)(h + c3 * DD))[lane];
        sx += (v0.x + v1.x) + (v2.x + v3.x);
        sy += (v0.y + v1.y) + (v2.y + v3.y);
    }
    for (; nn < e; nn++) {
        float2 v = ((const float2*)(h + col[nn] * DD))[lane];
        sx += v.x;
        sy += v.y;
    }
    float inv = (e > s) ? 1.f / (float)(e - s) : 0.f;
    ((float2*)(agg + w * DD))[lane] = make_float2(sx * inv, sy * inv);
}

// ---------------- node linear: out = x @ W^T + b (double-buffered) ----------------
__global__ __launch_bounds__(256, 2) void k_lin(
    const float* __restrict__ x, const float* __restrict__ W,
    const float* __restrict__ b, float* __restrict__ out, int n) {
    __shared__ __align__(16) float sh[2][4][DD];
    int tid = threadIdx.x;
    int g = tid >> 6;
    int j = tid & 63;

    float w[DD];
#pragma unroll
    for (int k = 0; k < DD; k += 4) {
        float4 a = *(const float4*)&W[j * DD + k];
        w[k] = a.x; w[k + 1] = a.y; w[k + 2] = a.z; w[k + 3] = a.w;
    }
    float bj = b[j];

    int stride = gridDim.x * 4;
    int i0 = blockIdx.x * 4 + g;
    float hv = 0.f;
    if (i0 < n) hv = x[i0 * DD + j];
    int buf = 0;
    for (int base = blockIdx.x * 4; base < n; base += stride) {
        int i = base + g;
        sh[buf][g][j] = hv;
        __syncthreads();
        int inx = i + stride;
        hv = (inx < n) ? x[inx * DD + j] : 0.f;
        if (i < n) {
            const float4* h4 = (const float4*)sh[buf][g];
            float a0 = 0.f, a1 = 0.f, a2 = 0.f, a3 = 0.f;
#pragma unroll
            for (int k4 = 0; k4 < 16; k4++) {
                float4 hvv = h4[k4];
                a0 += hvv.x * w[k4 * 4 + 0];
                a1 += hvv.y * w[k4 * 4 + 1];
                a2 += hvv.z * w[k4 * 4 + 2];
                a3 += hvv.w * w[k4 * 4 + 3];
            }
            out[i * DD + j] = (a0 + a1) + (a2 + a3) + bj;
        }
        buf ^= 1;
    }
}

// ---------------- dense SAGE transform: out = agg@Wl^T + bl + h@Wr^T ----------------
__global__ __launch_bounds__(256, 1) void k_gemm(
    const float* __restrict__ h, const float* __restrict__ agg,
    const float* __restrict__ Wl, const float* __restrict__ bl,
    const float* __restrict__ Wr, float* __restrict__ out, int n, int do_relu) {
    __shared__ __align__(16) float sh[2][4][DD];
    __shared__ __align__(16) float sa[2][4][DD];
    int tid = threadIdx.x;
    int g = tid >> 6;
    int j = tid & 63;

    float wl[DD], wr[DD];
#pragma unroll
    for (int k = 0; k < DD; k += 4) {
        float4 a = *(const float4*)&Wl[j * DD + k];
        wl[k] = a.x; wl[k + 1] = a.y; wl[k + 2] = a.z; wl[k + 3] = a.w;
        float4 c = *(const float4*)&Wr[j * DD + k];
        wr[k] = c.x; wr[k + 1] = c.y; wr[k + 2] = c.z; wr[k + 3] = c.w;
    }
    float bj = bl[j];

    int stride = gridDim.x * 4;
    int i0 = blockIdx.x * 4 + g;
    float hv = 0.f, av = 0.f;
    if (i0 < n) { hv = h[i0 * DD + j]; av = agg[i0 * DD + j]; }
    int buf = 0;
    for (int base = blockIdx.x * 4; base < n; base += stride) {
        int i = base + g;
        sh[buf][g][j] = hv;
        sa[buf][g][j] = av;
        __syncthreads();
        int inx = i + stride;
        if (inx < n) { hv = h[inx * DD + j]; av = agg[inx * DD + j]; }
        else         { hv = 0.f; av = 0.f; }
        if (i < n) {
            const float4* h4 = (const float4*)sh[buf][g];
            const float4* a4 = (const float4*)sa[buf][g];
            float a0 = 0.f, a1 = 0.f, a2 = 0.f, a3 = 0.f;
#pragma unroll
            for (int k4 = 0; k4 < 16; k4++) {
                float4 A = a4[k4];
                float4 H = h4[k4];
                a0 += A.x * wl[k4 * 4 + 0];
                a1 += A.y * wl[k4 * 4 + 1];
                a2 += A.z * wl[k4 * 4 + 2];
                a3 += A.w * wl[k4 * 4 + 3];
                a0 += H.x * wr[k4 * 4 + 0];
                a1 += H.y * wr[k4 * 4 + 1];
                a2 += H.z * wr[k4 * 4 + 2];
                a3 += H.w * wr[k4 * 4 + 3];
            }
            float r = (a0 + a1) + (a2 + a3) + bj;
            if (do_relu) r = fmaxf(r, 0.f);
            out[i * DD + j] = r;
        }
        buf ^= 1;
    }
}

// ---------------- edge dot product (warp per edge, float2 lanes) ----------------
__global__ __launch_bounds__(256) void k_edge(
    const float* __restrict__ h, const int* __restrict__ ea,
    const int* __restrict__ eb, float* __restrict__ out, int E) {
    int w = (blockIdx.x * blockDim.x + threadIdx.x) >> 5;
    int lane = threadIdx.x & 31;
    if (w >= E) return;
    int a = ea[w];
    int b = eb[w];
    float2 va = ((const float2*)(h + a * DD))[lane];
    float2 vb = ((const float2*)(h + b * DD))[lane];
    float p = va.x * vb.x + va.y * vb.y;
#pragma unroll
    for (int o = 16; o > 0; o >>= 1) p += __shfl_down_sync(0xffffffffu, p, o);
    if (lane == 0) out[w] = p;
}

// ---------------- launch ----------------
extern "C" void kernel_launch(void* const* d_in, const int* in_sizes, int n_in,
                              void* d_out, int out_size) {
    const float* x     = (const float*)d_in[0];
    const int*   ei    = (const int*)d_in[1];
    const int*   eli   = (const int*)d_in[2];
    const float* W_lin = (const float*)d_in[3];
    const float* b_lin = (const float*)d_in[4];
    const float* Wl1   = (const float*)d_in[5];
    const float* bl1   = (const float*)d_in[6];
    const float* Wr1   = (const float*)d_in[7];
    const float* Wl2   = (const float*)d_in[8];
    const float* bl2   = (const float*)d_in[9];
    const float* Wr2   = (const float*)d_in[10];

    int N  = in_sizes[0] / DD;      // 100000
    int E  = in_sizes[1] / 2;       // 1000000
    int EL = in_sizes[2] / 2;       // 200000

    const int* src = ei;            // edge_index[0] = source
    const int* dst = ei + E;        // edge_index[1] = target
    const int* ea  = eli;
    const int* eb  = eli + EL;

    float *h0, *h1, *agg;
    int *deg, *rowptr, *cursor, *col;
    cudaGetSymbolAddress((void**)&h0, g_h0);
    cudaGetSymbolAddress((void**)&h1, g_h1);
    cudaGetSymbolAddress((void**)&agg, g_agg);
    cudaGetSymbolAddress((void**)&deg, g_deg);
    cudaGetSymbolAddress((void**)&rowptr, g_rowptr);
    cudaGetSymbolAddress((void**)&cursor, g_cursor);
    cudaGetSymbolAddress((void**)&col, g_col);

    float* preds = (float*)d_out;

    // CSR build
    k_zero<<<256, 256>>>(deg, N);
    k_hist<<<2048, 256>>>(dst, deg, E);
    k_scan<<<1, 1024>>>(deg, rowptr, cursor, N);
    k_scatter<<<2048, 256>>>(src, dst, cursor, col, E);

    // node_lin
    k_lin<<<296, 256>>>(x, W_lin, b_lin, h0, N);

    // conv1 (relu)
    int agg_blocks = (N * 32 + 255) / 256;
    k_agg<<<agg_blocks, 256>>>(h0, rowptr, col, agg, N);
    k_gemm<<<148, 256>>>(h0, agg, Wl1, bl1, Wr1, h1, N, 1);

    // conv2 (no relu; reuse h0 as output buffer)
    k_agg<<<agg_blocks, 256>>>(h1, rowptr, col, agg, N);
    k_gemm<<<148, 256>>>(h1, agg, Wl2, bl2, Wr2, h0, N, 0);

    // edge classifier
    int blocks = (EL * 32 + 255) / 256;
    k_edge<<<blocks, 256>>>(h0, ea, eb, preds, EL);
}

// round 4
// speedup vs baseline: 2.6060x; 1.1216x over previous
#include <cuda_runtime.h>
#include <cuda_bf16.h>

#define NN 100000
#define DD 64
#define EMAX 1000000
#define SCAN_BLOCKS 200
#define SCAN_CHUNK 512   // SCAN_BLOCKS*SCAN_CHUNK = 102400 >= NN

// ---------------- device scratch (no allocation allowed) ----------------
__device__ float g_h0[NN * DD];
__device__ float g_h1[NN * DD];
__device__ float g_agg[NN * DD];
__device__ int   g_deg[NN];
__device__ int   g_rowptr[NN + 1];
__device__ int   g_cursor[NN];
__device__ int   g_col[EMAX];
__device__ int   g_part[256];
__device__ int   g_boff[256];

// ---------------- CSR build ----------------
__global__ void k_zero(int* p, int n) {
    for (int i = blockIdx.x * blockDim.x + threadIdx.x; i < n; i += gridDim.x * blockDim.x)
        p[i] = 0;
}

__global__ void k_hist(const int* __restrict__ dst, int* __restrict__ deg, int E) {
    for (int e = blockIdx.x * blockDim.x + threadIdx.x; e < E; e += gridDim.x * blockDim.x)
        atomicAdd(&deg[dst[e]], 1);
}

// phase 1: per-block partial sums of deg
__global__ void k_scan1(const int* __restrict__ deg, int* __restrict__ part, int n) {
    __shared__ int ps[256];
    int b = blockIdx.x;
    int t = threadIdx.x;
    int base = b * SCAN_CHUNK + t * 2;
    int s = 0;
    if (base < n)     s += deg[base];
    if (base + 1 < n) s += deg[base + 1];
    ps[t] = s;
    __syncthreads();
    for (int d = 1; d < 256; d <<= 1) {
        int v = (t >= d) ? ps[t - d] : 0;
        __syncthreads();
        ps[t] += v;
        __syncthreads();
    }
    if (t == 255) part[b] = ps[255];
}

// phase 2: scan the block partials (1 block)
__global__ void k_scan2(const int* __restrict__ part, int* __restrict__ boff,
                        int* __restrict__ rowptr, int n, int nblk) {
    __shared__ int ps[256];
    int t = threadIdx.x;
    ps[t] = (t < nblk) ? part[t] : 0;
    __syncthreads();
    for (int d = 1; d < 256; d <<= 1) {
        int v = (t >= d) ? ps[t - d] : 0;
        __syncthreads();
        ps[t] += v;
        __syncthreads();
    }
    boff[t] = (t == 0) ? 0 : ps[t - 1];
    if (t == 255) rowptr[n] = ps[255];
}

// phase 3: local scan + write rowptr/cursor
__global__ void k_scan3(const int* __restrict__ deg, const int* __restrict__ boff,
                        int* __restrict__ rowptr, int* __restrict__ cursor, int n) {
    __shared__ int ps[256];
    int b = blockIdx.x;
    int t = threadIdx.x;
    int base = b * SCAN_CHUNK + t * 2;
    int d0 = (base < n) ? deg[base] : 0;
    int d1 = (base + 1 < n) ? deg[base + 1] : 0;
    ps[t] = d0 + d1;
    __syncthreads();
    for (int d = 1; d < 256; d <<= 1) {
        int v = (t >= d) ? ps[t - d] : 0;
        __syncthreads();
        ps[t] += v;
        __syncthreads();
    }
    int off = boff[b] + ((t == 0) ? 0 : ps[t - 1]);
    if (base < n)     { rowptr[base] = off;          cursor[base] = off; }
    if (base + 1 < n) { rowptr[base + 1] = off + d0; cursor[base + 1] = off + d0; }
}

__global__ void k_scatter(const int* __restrict__ src, const int* __restrict__ dst,
                          int* __restrict__ cursor, int* __restrict__ col, int E) {
    for (int e = blockIdx.x * blockDim.x + threadIdx.x; e < E; e += gridDim.x * blockDim.x) {
        int d = dst[e];
        int p = atomicAdd(&cursor[d], 1);
        col[p] = src[e];
    }
}

// ---------------- mean aggregation: half-warp per node, float4 lanes ----------------
__global__ __launch_bounds__(256) void k_agg(
    const float* __restrict__ h, const int* __restrict__ rowptr,
    const int* __restrict__ col, float* __restrict__ agg, int n) {
    int node = (blockIdx.x * blockDim.x + threadIdx.x) >> 4;
    int l = threadIdx.x & 15;
    if (node >= n) return;
    int s = rowptr[node];
    int e = rowptr[node + 1];
    float ax = 0.f, ay = 0.f, az = 0.f, aw = 0.f;
    int nn = s;
    for (; nn + 4 <= e; nn += 4) {
        int c0 = col[nn], c1 = col[nn + 1], c2 = col[nn + 2], c3 = col[nn + 3];
        float4 v0 = ((const float4*)(h + c0 * DD))[l];
        float4 v1 = ((const float4*)(h + c1 * DD))[l];
        float4 v2 = ((const float4*)(h + c2 * DD))[l];
        float4 v3 = ((const float4*)(h + c3 * DD))[l];
        ax += (v0.x + v1.x) + (v2.x + v3.x);
        ay += (v0.y + v1.y) + (v2.y + v3.y);
        az += (v0.z + v1.z) + (v2.z + v3.z);
        aw += (v0.w + v1.w) + (v2.w + v3.w);
    }
    for (; nn < e; nn++) {
        float4 v = ((const float4*)(h + col[nn] * DD))[l];
        ax += v.x; ay += v.y; az += v.z; aw += v.w;
    }
    float inv = (e > s) ? 1.f / (float)(e - s) : 0.f;
    ((float4*)(agg + node * DD))[l] = make_float4(ax * inv, ay * inv, az * inv, aw * inv);
}

// ---------------- node linear: out = x @ W^T + b (double-buffered) ----------------
__global__ __launch_bounds__(256, 2) void k_lin(
    const float* __restrict__ x, const float* __restrict__ W,
    const float* __restrict__ b, float* __restrict__ out, int n) {
    __shared__ __align__(16) float sh[2][4][DD];
    int tid = threadIdx.x;
    int g = tid >> 6;
    int j = tid & 63;

    float w[DD];
#pragma unroll
    for (int k = 0; k < DD; k += 4) {
        float4 a = *(const float4*)&W[j * DD + k];
        w[k] = a.x; w[k + 1] = a.y; w[k + 2] = a.z; w[k + 3] = a.w;
    }
    float bj = b[j];

    int stride = gridDim.x * 4;
    int i0 = blockIdx.x * 4 + g;
    float hv = 0.f;
    if (i0 < n) hv = x[i0 * DD + j];
    int buf = 0;
    for (int base = blockIdx.x * 4; base < n; base += stride) {
        int i = base + g;
        sh[buf][g][j] = hv;
        __syncthreads();
        int inx = i + stride;
        hv = (inx < n) ? x[inx * DD + j] : 0.f;
        if (i < n) {
            const float4* h4 = (const float4*)sh[buf][g];
            float a0 = 0.f, a1 = 0.f, a2 = 0.f, a3 = 0.f;
#pragma unroll
            for (int k4 = 0; k4 < 16; k4++) {
                float4 hvv = h4[k4];
                a0 += hvv.x * w[k4 * 4 + 0];
                a1 += hvv.y * w[k4 * 4 + 1];
                a2 += hvv.z * w[k4 * 4 + 2];
                a3 += hvv.w * w[k4 * 4 + 3];
            }
            out[i * DD + j] = (a0 + a1) + (a2 + a3) + bj;
        }
        buf ^= 1;
    }
}

// ---------------- dense SAGE transform: out = agg@Wl^T + bl + h@Wr^T ----------------
// 8 nodes per block-iteration; each thread computes col j for 2 nodes.
__global__ __launch_bounds__(256, 1) void k_gemm(
    const float* __restrict__ h, const float* __restrict__ agg,
    const float* __restrict__ Wl, const float* __restrict__ bl,
    const float* __restrict__ Wr, float* __restrict__ out, int n, int do_relu) {
    __shared__ __align__(16) float sh[2][8][DD];
    __shared__ __align__(16) float sa[2][8][DD];
    int tid = threadIdx.x;
    int g = tid >> 6;       // 0..3
    int j = tid & 63;

    float wl[DD], wr[DD];
#pragma unroll
    for (int k = 0; k < DD; k += 4) {
        float4 a = *(const float4*)&Wl[j * DD + k];
        wl[k] = a.x; wl[k + 1] = a.y; wl[k + 2] = a.z; wl[k + 3] = a.w;
        float4 c = *(const float4*)&Wr[j * DD + k];
        wr[k] = c.x; wr[k + 1] = c.y; wr[k + 2] = c.z; wr[k + 3] = c.w;
    }
    float bj = bl[j];

    int stride = gridDim.x * 8;
    int iA0 = blockIdx.x * 8 + g;
    int iB0 = iA0 + 4;
    float hvA = 0.f, avA = 0.f, hvB = 0.f, avB = 0.f;
    if (iA0 < n) { hvA = h[iA0 * DD + j]; avA = agg[iA0 * DD + j]; }
    if (iB0 < n) { hvB = h[iB0 * DD + j]; avB = agg[iB0 * DD + j]; }
    int buf = 0;
    for (int base = blockIdx.x * 8; base < n; base += stride) {
        int iA = base + g;
        int iB = iA + 4;
        sh[buf][g][j] = hvA;
        sa[buf][g][j] = avA;
        sh[buf][g + 4][j] = hvB;
        sa[buf][g + 4][j] = avB;
        __syncthreads();
        int nA = iA + stride, nB = iB + stride;
        if (nA < n) { hvA = h[nA * DD + j]; avA = agg[nA * DD + j]; }
        else        { hvA = 0.f; avA = 0.f; }
        if (nB < n) { hvB = h[nB * DD + j]; avB = agg[nB * DD + j]; }
        else        { hvB = 0.f; avB = 0.f; }

        const float4* h4A = (const float4*)sh[buf][g];
        const float4* a4A = (const float4*)sa[buf][g];
        const float4* h4B = (const float4*)sh[buf][g + 4];
        const float4* a4B = (const float4*)sa[buf][g + 4];
        float A0 = 0.f, A1 = 0.f, A2 = 0.f, A3 = 0.f;
        float B0 = 0.f, B1 = 0.f, B2 = 0.f, B3 = 0.f;
#pragma unroll
        for (int k4 = 0; k4 < 16; k4++) {
            float4 aA = a4A[k4];
            float4 hA = h4A[k4];
            float4 aB = a4B[k4];
            float4 hB = h4B[k4];
            float w0 = wl[k4 * 4 + 0], w1 = wl[k4 * 4 + 1];
            float w2 = wl[k4 * 4 + 2], w3 = wl[k4 * 4 + 3];
            float r0 = wr[k4 * 4 + 0], r1 = wr[k4 * 4 + 1];
            float r2 = wr[k4 * 4 + 2], r3 = wr[k4 * 4 + 3];
            A0 += aA.x * w0; A1 += aA.y * w1; A2 += aA.z * w2; A3 += aA.w * w3;
            A0 += hA.x * r0; A1 += hA.y * r1; A2 += hA.z * r2; A3 += hA.w * r3;
            B0 += aB.x * w0; B1 += aB.y * w1; B2 += aB.z * w2; B3 += aB.w * w3;
            B0 += hB.x * r0; B1 += hB.y * r1; B2 += hB.z * r2; B3 += hB.w * r3;
        }
        if (iA < n) {
            float r = (A0 + A1) + (A2 + A3) + bj;
            if (do_relu) r = fmaxf(r, 0.f);
            out[iA * DD + j] = r;
        }
        if (iB < n) {
            float r = (B0 + B1) + (B2 + B3) + bj;
            if (do_relu) r = fmaxf(r, 0.f);
            out[iB * DD + j] = r;
        }
        buf ^= 1;
    }
}

// ---------------- edge dot product (warp per edge, float2 lanes) ----------------
__global__ __launch_bounds__(256) void k_edge(
    const float* __restrict__ h, const int* __restrict__ ea,
    const int* __restrict__ eb, float* __restrict__ out, int E) {
    int w = (blockIdx.x * blockDim.x + threadIdx.x) >> 5;
    int lane = threadIdx.x & 31;
    if (w >= E) return;
    int a = ea[w];
    int b = eb[w];
    float2 va = ((const float2*)(h + a * DD))[lane];
    float2 vb = ((const float2*)(h + b * DD))[lane];
    float p = va.x * vb.x + va.y * vb.y;
#pragma unroll
    for (int o = 16; o > 0; o >>= 1) p += __shfl_down_sync(0xffffffffu, p, o);
    if (lane == 0) out[w] = p;
}

// ---------------- launch ----------------
extern "C" void kernel_launch(void* const* d_in, const int* in_sizes, int n_in,
                              void* d_out, int out_size) {
    const float* x     = (const float*)d_in[0];
    const int*   ei    = (const int*)d_in[1];
    const int*   eli   = (const int*)d_in[2];
    const float* W_lin = (const float*)d_in[3];
    const float* b_lin = (const float*)d_in[4];
    const float* Wl1   = (const float*)d_in[5];
    const float* bl1   = (const float*)d_in[6];
    const float* Wr1   = (const float*)d_in[7];
    const float* Wl2   = (const float*)d_in[8];
    const float* bl2   = (const float*)d_in[9];
    const float* Wr2   = (const float*)d_in[10];

    int N  = in_sizes[0] / DD;      // 100000
    int E  = in_sizes[1] / 2;       // 1000000
    int EL = in_sizes[2] / 2;       // 200000

    const int* src = ei;            // edge_index[0] = source
    const int* dst = ei + E;        // edge_index[1] = target
    const int* ea  = eli;
    const int* eb  = eli + EL;

    float *h0, *h1, *agg;
    int *deg, *rowptr, *cursor, *col, *part, *boff;
    cudaGetSymbolAddress((void**)&h0, g_h0);
    cudaGetSymbolAddress((void**)&h1, g_h1);
    cudaGetSymbolAddress((void**)&agg, g_agg);
    cudaGetSymbolAddress((void**)&deg, g_deg);
    cudaGetSymbolAddress((void**)&rowptr, g_rowptr);
    cudaGetSymbolAddress((void**)&cursor, g_cursor);
    cudaGetSymbolAddress((void**)&col, g_col);
    cudaGetSymbolAddress((void**)&part, g_part);
    cudaGetSymbolAddress((void**)&boff, g_boff);

    float* preds = (float*)d_out;

    int nblk = (N + SCAN_CHUNK - 1) / SCAN_CHUNK;   // 196 <= 256

    // CSR build
    k_zero<<<256, 256>>>(deg, N);
    k_hist<<<2048, 256>>>(dst, deg, E);
    k_scan1<<<nblk, 256>>>(deg, part, N);
    k_scan2<<<1, 256>>>(part, boff, rowptr, N, nblk);
    k_scan3<<<nblk, 256>>>(deg, boff, rowptr, cursor, N);
    k_scatter<<<2048, 256>>>(src, dst, cursor, col, E);

    // node_lin
    k_lin<<<296, 256>>>(x, W_lin, b_lin, h0, N);

    // conv1 (relu)
    int agg_blocks = (N * 16 + 255) / 256;
    k_agg<<<agg_blocks, 256>>>(h0, rowptr, col, agg, N);
    k_gemm<<<148, 256>>>(h0, agg, Wl1, bl1, Wr1, h1, N, 1);

    // conv2 (no relu; reuse h0 as output buffer)
    k_agg<<<agg_blocks, 256>>>(h1, rowptr, col, agg, N);
    k_gemm<<<148, 256>>>(h1, agg, Wl2, bl2, Wr2, h0, N, 0);

    // edge classifier
    int blocks = (EL * 32 + 255) / 256;
    k_edge<<<blocks, 256>>>(h0, ea, eb, preds, EL);
}